// round 12
// baseline (speedup 1.0000x reference)
#include <cuda_runtime.h>
#include <cuda_fp16.h>
#include <math.h>
#include <cstdint>

// ---------------------------------------------------------------------------
// Problem constants: B=8192, T=15, D=H=512, MAXL=8, CENTER=7
// ---------------------------------------------------------------------------
#define B_MAX   8192
#define T_WIN   15
#define D_DIM   512
#define H_DIM   512
#define G3      1536
#define MAXL    8

#define PITCH_H      40                    // smem row pitch in halfs (80 B)
#define STAGES       4                     // K32 stages
#define STAGE_HALFS  (128 * PITCH_H)       // 5120 halfs = 10240 B
#define SMEM_REQ     (STAGES * STAGE_HALFS * 2 * 2)   // 81920 B
// fused kernel: 4 stages x [A|Br|Bz|Bn] x (64 x PITCH_H) halfs = same 81920 B
#define F_TILE_HALFS (64 * PITCH_H)

// ---------------------------------------------------------------------------
// Scratch
// ---------------------------------------------------------------------------
__device__ __half g_xp0[B_MAX * MAXL * G3];   // [t][sorted_i][1536] fwd
__device__ __half g_xp1[B_MAX * MAXL * G3];
__device__ __half g_h0a[B_MAX * H_DIM];       // fwd h buffers (parity)
__device__ __half g_h0b[B_MAX * H_DIM];
__device__ __half g_h1a[B_MAX * H_DIM];       // bwd
__device__ __half g_h1b[B_MAX * H_DIM];
__device__ __half g_hid[B_MAX * H_DIM];       // MLP hidden
__device__ __half g_winh[B_MAX * T_WIN * D_DIM];
#define WH_WIHF 0
#define WH_WHHF (G3 * D_DIM)
#define WH_WIHB (2 * G3 * D_DIM)
#define WH_WHHB (3 * G3 * D_DIM)
#define WH_W1   (4 * G3 * D_DIM)
#define WH_W2   (4 * G3 * D_DIM + H_DIM * 2 * H_DIM)
__device__ __half g_wh[4 * G3 * D_DIM + H_DIM * 2 * H_DIM + H_DIM * H_DIM];

// ---- length-compaction state ----
#define MAX_CHUNKS 64
__device__ int g_chunk_hist[MAX_CHUNKS][16];
__device__ int g_chunk_base[MAX_CHUNKS][16];
__device__ int g_lrank [B_MAX];
__device__ int g_perm  [B_MAX];
__device__ int g_lenf_s[B_MAX];
__device__ int g_lenb_s[B_MAX];
__device__ int g_nt[2 * MAXL];

// ---------------------------------------------------------------------------
// PTX helpers
// ---------------------------------------------------------------------------
__device__ __forceinline__ void ldsm4(unsigned* r, const __half* p) {
    unsigned addr = (unsigned)__cvta_generic_to_shared(p);
    asm volatile("ldmatrix.sync.aligned.m8n8.x4.shared.b16 {%0,%1,%2,%3}, [%4];"
                 : "=r"(r[0]), "=r"(r[1]), "=r"(r[2]), "=r"(r[3]) : "r"(addr));
}

__device__ __forceinline__ void mma_f16(float* c, const unsigned* a,
                                        unsigned b0, unsigned b1) {
    asm volatile(
        "mma.sync.aligned.m16n8k16.row.col.f32.f16.f16.f32 "
        "{%0,%1,%2,%3}, {%4,%5,%6,%7}, {%8,%9}, {%0,%1,%2,%3};"
        : "+f"(c[0]), "+f"(c[1]), "+f"(c[2]), "+f"(c[3])
        : "r"(a[0]), "r"(a[1]), "r"(a[2]), "r"(a[3]), "r"(b0), "r"(b1));
}

__device__ __forceinline__ void cpasync16(void* sp, const void* gp) {
    unsigned sa = (unsigned)__cvta_generic_to_shared(sp);
    asm volatile("cp.async.cg.shared.global [%0], [%1], 16;"
                 :: "r"(sa), "l"(gp) : "memory");
}
#define CP_COMMIT() asm volatile("cp.async.commit_group;" ::: "memory")
#define CP_WAIT(N)  asm volatile("cp.async.wait_group %0;" :: "n"(N) : "memory")

__device__ __forceinline__ float4 ldh4(const __half* p) {
    __half2 a = *(const __half2*)(p);
    __half2 b = *(const __half2*)(p + 2);
    float2 fa = __half22float2(a);
    float2 fb = __half22float2(b);
    return make_float4(fa.x, fa.y, fb.x, fb.y);
}

// ---------------------------------------------------------------------------
// Masked window convert
// ---------------------------------------------------------------------------
__global__ void win2half(const float4* __restrict__ win,
                         uint2* __restrict__ dst,
                         const int* __restrict__ wlen) {
    const int row = blockIdx.x;
    const int b   = row / T_WIN;
    const int pos = row % T_WIN;
    const int wl  = wlen[b];
    const int lo  = 7 - (wl - 1) / 2;
    const int hi  = 7 + wl / 2;
    if (pos < lo || pos > hi) return;
    const int tid = threadIdx.x;
    float4 v = win[(size_t)row * 128 + tid];
    __half2 h0 = __floats2half2_rn(v.x, v.y);
    __half2 h1 = __floats2half2_rn(v.z, v.w);
    uint2 o;
    o.x = *(unsigned*)&h0; o.y = *(unsigned*)&h1;
    dst[(size_t)row * 128 + tid] = o;
}

// ---------------------------------------------------------------------------
// All 6 weight matrices converted in ONE launch
// ---------------------------------------------------------------------------
struct W6 {
    const float4* src[6];
    uint4*        dst[6];
    int           n8[6];
};

__global__ void weights2half(W6 w) {
    int i = blockIdx.x * blockDim.x + threadIdx.x;
    #pragma unroll
    for (int s = 0; s < 6; ++s) {
        if (i < w.n8[s]) {
            float4 a = w.src[s][2 * i], b = w.src[s][2 * i + 1];
            __half2 h0 = __floats2half2_rn(a.x, a.y);
            __half2 h1 = __floats2half2_rn(a.z, a.w);
            __half2 h2 = __floats2half2_rn(b.x, b.y);
            __half2 h3 = __floats2half2_rn(b.z, b.w);
            uint4 o;
            o.x = *(unsigned*)&h0; o.y = *(unsigned*)&h1;
            o.z = *(unsigned*)&h2; o.w = *(unsigned*)&h3;
            w.dst[s][i] = o;
            return;
        }
        i -= w.n8[s];
    }
}

// ---------------------------------------------------------------------------
// Deterministic counting sort by window_len descending
// ---------------------------------------------------------------------------
__global__ void sort1(const int* __restrict__ wlen) {
    __shared__ int s_wl[256];
    __shared__ int s_rank[256];
    __shared__ int s_h[16];
    const int c = blockIdx.x, tid = threadIdx.x;
    s_wl[tid] = wlen[c * 256 + tid];
    if (tid < 16) s_h[tid] = 0;
    __syncthreads();
    if (tid == 0) {
        #pragma unroll 4
        for (int k = 0; k < 256; ++k) { int w = s_wl[k]; s_rank[k] = s_h[w]++; }
    }
    __syncthreads();
    g_lrank[c * 256 + tid] = s_rank[tid];
    if (tid < 16) g_chunk_hist[c][tid] = s_h[tid];
}

__global__ void sort2(int nchunks) {
    const int tid = threadIdx.x;
    __shared__ int total[16];
    __shared__ int wbase[16];
    if (tid < 16) {
        int s = 0;
        #pragma unroll 8
        for (int c = 0; c < nchunks; ++c) s += g_chunk_hist[c][tid];
        total[tid] = s;
    }
    __syncthreads();
    if (tid == 0) {
        int off = 0;
        for (int w = 15; w >= 1; --w) { wbase[w] = off; off += total[w]; }
    }
    __syncthreads();
    if (tid >= 1 && tid <= 15) {
        int run = wbase[tid];
        for (int c = 0; c < nchunks; ++c) {
            g_chunk_base[c][tid] = run;
            run += g_chunk_hist[c][tid];
        }
    }
    if (tid < MAXL) {
        int nf = 0, nb = 0;
        #pragma unroll
        for (int w = 1; w <= 15; ++w) {
            if ((w - 1) / 2 + 1 > tid) nf += total[w];
            if (w / 2 + 1 > tid)       nb += total[w];
        }
        g_nt[tid]        = nf;
        g_nt[MAXL + tid] = nb;
    }
}

__global__ void sort3(const int* __restrict__ wlen) {
    const int c = blockIdx.x;
    const int i = c * 256 + threadIdx.x;
    const int w = wlen[i];
    const int pos = g_chunk_base[c][w] + g_lrank[i];
    g_perm[pos]   = i;
    g_lenf_s[pos] = (w - 1) / 2 + 1;
    g_lenb_s[pos] = w / 2 + 1;
}

// ---------------------------------------------------------------------------
// fp16 tensor-core NT GEMM (gather / concat / plain)
// ---------------------------------------------------------------------------
enum { MODE_GATHER = 0, MODE_PLAIN = 1, MODE_CONCAT = 2 };
enum { EPI_NONE = 0, EPI_BIAS = 1, EPI_BIAS_RELU = 2 };

struct GemmP {
    const __half* A0;     // PLAIN: A | CONCAT: h_f bufA
    const __half* A0b;    // CONCAT: h_f bufB
    const __half* A1;     // CONCAT: h_b bufA
    const __half* A1b;    // CONCAT: h_b bufB
    const __half* B0;
    const __half* B1;
    void*         C0;
    void*         C1;
    const __half* win;
    const float*  bias;
    const int*    perm;
    const int*    lenf_s;
    const int*    lenb_s;
    const int*    nt;
    const int*    operm;
    int M, N, K, step, Bn;
};

template<int MODE, int EPI, int OUTH>
__global__ __launch_bounds__(256, 2)
void gemm_f16(GemmP p)
{
    const int dir = blockIdx.z;
    const int bm  = blockIdx.y;
    const int bn  = blockIdx.x;

    if (MODE == MODE_GATHER) {
        if (bm * 128 >= p.nt[dir * MAXL + p.step]) return;
    }

    extern __shared__ __half hsm[];
    __half* As = hsm;
    __half* Bs = hsm + STAGES * STAGE_HALFS;

    const __half* __restrict__ Bmat = dir ? p.B1 : p.B0;
    const int K = p.K;
    const int N = p.N;

    const int tid  = threadIdx.x;
    const int warp = tid >> 5;
    const int lane = tid & 31;
    const int wm   = (warp >> 1) * 32;
    const int wn   = (warp & 1) * 64;

    const int lr = tid >> 2;
    const int lc = (tid & 3) * 8;

    const __half* arow0 = nullptr;
    const __half* arow1 = nullptr;
    const __half* ab0 = nullptr;
    const __half* ab1 = nullptr;

    if (MODE == MODE_GATHER) {
        const int t = p.step;
        #pragma unroll
        for (int q = 0; q < 2; ++q) {
            const int i   = bm * 128 + lr + q * 64;
            const int b   = p.perm[i];
            const int len = dir ? p.lenb_s[i] : p.lenf_s[i];
            int idx = dir ? (6 + len - t) : (8 - len + t);
            idx = min(max(idx, 0), T_WIN - 1);
            const __half* rp = p.win + ((size_t)b * T_WIN + idx) * D_DIM;
            if (q == 0) arow0 = rp; else arow1 = rp;
        }
    } else if (MODE == MODE_PLAIN) {
        arow0 = (dir ? p.A1 : p.A0) + (size_t)(bm * 128 + lr) * K;
        arow1 = arow0 + (size_t)64 * K;
    } else {   // CONCAT with per-row parity buffer select
        #pragma unroll
        for (int q = 0; q < 2; ++q) {
            const int r  = bm * 128 + lr + q * 64;
            const int lf = p.lenf_s[r];
            const int lb = p.lenb_s[r];
            const __half* fb = ((lf - 1) & 1) ? p.A0b : p.A0;
            const __half* bb = ((lb - 1) & 1) ? p.A1b : p.A1;
            if (q == 0) { arow0 = fb + (size_t)r * 512; ab0 = bb + (size_t)r * 512; }
            else        { arow1 = fb + (size_t)r * 512; ab1 = bb + (size_t)r * 512; }
        }
    }

    const __half* brow0 = Bmat + (size_t)(bn * 128 + lr) * K;
    const __half* brow1 = brow0 + (size_t)64 * K;

    float acc[2][8][4];
    #pragma unroll
    for (int i = 0; i < 2; ++i)
        #pragma unroll
        for (int t = 0; t < 8; ++t)
            #pragma unroll
            for (int v = 0; v < 4; ++v) acc[i][t][v] = 0.f;

    const int KT = K >> 5;

#define LOAD_STAGE(S, KI)                                                      \
    do {                                                                       \
        if ((KI) < KT) {                                                       \
            const int K0 = (KI) * 32;                                          \
            __half* da = As + (S) * STAGE_HALFS + lr * PITCH_H + lc;           \
            __half* db = Bs + (S) * STAGE_HALFS + lr * PITCH_H + lc;           \
            const __half *pa0, *pa1;                                           \
            if (MODE == MODE_CONCAT) {                                         \
                pa0 = ((K0 < 512) ? arow0 : ab0) + (K0 & 511) + lc;            \
                pa1 = ((K0 < 512) ? arow1 : ab1) + (K0 & 511) + lc;            \
            } else {                                                           \
                pa0 = arow0 + K0 + lc;                                         \
                pa1 = arow1 + K0 + lc;                                         \
            }                                                                  \
            cpasync16(da,                pa0);                                 \
            cpasync16(da + 64 * PITCH_H, pa1);                                 \
            cpasync16(db,                brow0 + K0 + lc);                     \
            cpasync16(db + 64 * PITCH_H, brow1 + K0 + lc);                     \
        }                                                                      \
        CP_COMMIT();                                                           \
    } while (0)

    #pragma unroll
    for (int s = 0; s < STAGES - 1; ++s) LOAD_STAGE(s, s);

    for (int kt = 0; kt < KT; ++kt) {
        CP_WAIT(STAGES - 2);
        __syncthreads();

        const int buf = kt & (STAGES - 1);
        const __half* Ab = As + buf * STAGE_HALFS;
        const __half* Bb = Bs + buf * STAGE_HALFS;

        #pragma unroll
        for (int ks = 0; ks < 2; ++ks) {
            const int k0 = ks * 16;
            unsigned a[2][4];
            #pragma unroll
            for (int i = 0; i < 2; ++i)
                ldsm4(a[i], Ab + (wm + i * 16 + (lane & 15)) * PITCH_H
                               + k0 + (lane >> 4) * 8);
            unsigned b[4][4];
            #pragma unroll
            for (int t4 = 0; t4 < 4; ++t4)
                ldsm4(b[t4], Bb + (wn + t4 * 16 + ((lane >> 4) << 3)
                                   + (lane & 7)) * PITCH_H
                                + k0 + ((lane >> 3) & 1) * 8);
            #pragma unroll
            for (int i = 0; i < 2; ++i)
                #pragma unroll
                for (int t4 = 0; t4 < 4; ++t4) {
                    mma_f16(acc[i][2 * t4],     a[i], b[t4][0], b[t4][1]);
                    mma_f16(acc[i][2 * t4 + 1], a[i], b[t4][2], b[t4][3]);
                }
        }

        LOAD_STAGE((kt + STAGES - 1) & (STAGES - 1), kt + STAGES - 1);
    }
#undef LOAD_STAGE

    const int qr = lane >> 2;
    const int qc = (lane & 3) * 2;
    #pragma unroll
    for (int i = 0; i < 2; ++i) {
        const int rA = bm * 128 + wm + i * 16 + qr;
        const int gA = p.operm ? p.operm[rA]     : rA;
        const int gB = p.operm ? p.operm[rA + 8] : rA + 8;
        #pragma unroll
        for (int t = 0; t < 8; ++t) {
            const int cc = bn * 128 + wn + t * 8 + qc;
            float v0 = acc[i][t][0], v1 = acc[i][t][1];
            float v2 = acc[i][t][2], v3 = acc[i][t][3];
            if (EPI != EPI_NONE) {
                float b0 = p.bias[cc], b1 = p.bias[cc + 1];
                v0 += b0; v1 += b1; v2 += b0; v3 += b1;
                if (EPI == EPI_BIAS_RELU) {
                    v0 = fmaxf(v0, 0.f); v1 = fmaxf(v1, 0.f);
                    v2 = fmaxf(v2, 0.f); v3 = fmaxf(v3, 0.f);
                }
            }
            if (OUTH) {
                __half* Ch = (__half*)(dir ? p.C1 : p.C0);
                *(__half2*)(Ch + (size_t)gA * N + cc) = __floats2half2_rn(v0, v1);
                *(__half2*)(Ch + (size_t)gB * N + cc) = __floats2half2_rn(v2, v3);
            } else {
                float* Cf = (float*)(dir ? p.C1 : p.C0);
                *(float2*)(Cf + (size_t)gA * N + cc) = make_float2(v0, v1);
                *(float2*)(Cf + (size_t)gB * N + cc) = make_float2(v2, v3);
            }
        }
    }
}

// ---------------------------------------------------------------------------
// Fused recurrence step: gh = h_in @ Whh^T (r,z,n blocks) + GRU gate -> h_out
// Tile: 64 rows x 64 gate-cols x 3 gates. 256 thr, 2 CTAs/SM, 4-stage pipe.
// Warp tile 32(M) x 16(N). acc = 48 regs/thread.
// ---------------------------------------------------------------------------
struct FuseP {
    const __half* hin0;  const __half* hin1;
    __half*       hout0; __half*       hout1;
    const __half* W0;    const __half* W1;     // Whh fp16 (1536,512)
    const __half* xp0;   const __half* xp1;
    const float*  bih0;  const float*  bih1;
    const float*  bhh0;  const float*  bhh1;
    const int*    nt;
    int t, Bn;
};

__global__ __launch_bounds__(256, 2)
void gemm_rec_fused(FuseP p)
{
    const int dir = blockIdx.z, bm = blockIdx.y, bn = blockIdx.x;
    const int t    = p.t;
    const int nact = p.nt[dir * MAXL + t];
    if (bm * 64 >= nact) return;

    extern __shared__ __half hsm[];   // stage: [A | Br | Bz | Bn] x (64*PITCH_H)

    const __half* hin  = dir ? p.hin1  : p.hin0;
    __half*       hout = dir ? p.hout1 : p.hout0;
    const __half* W    = dir ? p.W1    : p.W0;
    const __half* xp   = dir ? p.xp1   : p.xp0;
    const float*  bih  = dir ? p.bih1  : p.bih0;
    const float*  bhh  = dir ? p.bhh1  : p.bhh0;

    const int tid  = threadIdx.x;
    const int warp = tid >> 5, lane = tid & 31;
    const int wm   = (warp & 1) * 32;     // M offset in 64
    const int wn   = (warp >> 1) * 16;    // N offset in 64

    // load mapping: thread -> one row of one matrix, full 32-half K chunk
    const int mat = tid >> 6;             // 0=A(h), 1..3=gate r/z/n
    const int row = tid & 63;
    const __half* grow;
    if (mat == 0) grow = hin + (size_t)(bm * 64 + row) * H_DIM;
    else          grow = W + (size_t)((mat - 1) * 512 + bn * 64 + row) * H_DIM;

    float acc[3][2][2][4];
    #pragma unroll
    for (int g = 0; g < 3; ++g)
        #pragma unroll
        for (int i = 0; i < 2; ++i)
            #pragma unroll
            for (int n = 0; n < 2; ++n)
                #pragma unroll
                for (int v = 0; v < 4; ++v) acc[g][i][n][v] = 0.f;

    const int KT = H_DIM >> 5;    // 16

#define F_LOAD(S, KI)                                                          \
    do {                                                                       \
        if ((KI) < KT) {                                                       \
            const int K0 = (KI) * 32;                                          \
            __half* d = hsm + (S) * 4 * F_TILE_HALFS + mat * F_TILE_HALFS      \
                      + row * PITCH_H;                                         \
            const __half* s = grow + K0;                                       \
            cpasync16(d,      s);                                              \
            cpasync16(d + 8,  s + 8);                                          \
            cpasync16(d + 16, s + 16);                                         \
            cpasync16(d + 24, s + 24);                                         \
        }                                                                      \
        CP_COMMIT();                                                           \
    } while (0)

    #pragma unroll
    for (int s = 0; s < STAGES - 1; ++s) F_LOAD(s, s);

    for (int kt = 0; kt < KT; ++kt) {
        CP_WAIT(STAGES - 2);
        __syncthreads();

        const __half* base = hsm + (kt & (STAGES - 1)) * 4 * F_TILE_HALFS;

        #pragma unroll
        for (int ks = 0; ks < 2; ++ks) {
            const int k0 = ks * 16;
            unsigned a[2][4];
            #pragma unroll
            for (int i = 0; i < 2; ++i)
                ldsm4(a[i], base + (wm + i * 16 + (lane & 15)) * PITCH_H
                                 + k0 + (lane >> 4) * 8);
            #pragma unroll
            for (int g = 0; g < 3; ++g) {
                unsigned b[4];
                ldsm4(b, base + (g + 1) * F_TILE_HALFS
                             + (wn + ((lane >> 4) << 3) + (lane & 7)) * PITCH_H
                             + k0 + ((lane >> 3) & 1) * 8);
                #pragma unroll
                for (int i = 0; i < 2; ++i) {
                    mma_f16(acc[g][i][0], a[i], b[0], b[1]);
                    mma_f16(acc[g][i][1], a[i], b[2], b[3]);
                }
            }
        }

        F_LOAD((kt + STAGES - 1) & (STAGES - 1), kt + STAGES - 1);
    }
#undef F_LOAD

    // ---- fused GRU gate epilogue (gh in fp32 registers) ----
    const int qr = lane >> 2;
    const int qc = (lane & 3) * 2;
    #pragma unroll
    for (int i = 0; i < 2; ++i) {
        const int r0 = bm * 64 + wm + i * 16 + qr;
        #pragma unroll
        for (int n = 0; n < 2; ++n) {
            const int c = bn * 64 + wn + n * 8 + qc;   // gate col in [0,512)
            const float2 br2 = *(const float2*)(bih + c);
            const float2 bz2 = *(const float2*)(bih + 512 + c);
            const float2 bq2 = *(const float2*)(bih + 1024 + c);
            const float2 cr2 = *(const float2*)(bhh + c);
            const float2 cz2 = *(const float2*)(bhh + 512 + c);
            const float2 cq2 = *(const float2*)(bhh + 1024 + c);
            #pragma unroll
            for (int half = 0; half < 2; ++half) {
                const int r = r0 + half * 8;
                if (r >= nact) continue;
                const float ghr0 = acc[0][i][n][half * 2];
                const float ghr1 = acc[0][i][n][half * 2 + 1];
                const float ghz0 = acc[1][i][n][half * 2];
                const float ghz1 = acc[1][i][n][half * 2 + 1];
                const float ghn0 = acc[2][i][n][half * 2];
                const float ghn1 = acc[2][i][n][half * 2 + 1];
                const __half* xq = xp + ((size_t)t * p.Bn + r) * G3 + c;
                float2 xr2 = __half22float2(*(const __half2*)(xq));
                float2 xz2 = __half22float2(*(const __half2*)(xq + 512));
                float2 xn2 = __half22float2(*(const __half2*)(xq + 1024));
                float2 hp2 = __half22float2(
                    *(const __half2*)(hin + (size_t)r * H_DIM + c));

                float rr0 = 1.f / (1.f + expf(-(xr2.x + br2.x + ghr0 + cr2.x)));
                float rr1 = 1.f / (1.f + expf(-(xr2.y + br2.y + ghr1 + cr2.y)));
                float zz0 = 1.f / (1.f + expf(-(xz2.x + bz2.x + ghz0 + cz2.x)));
                float zz1 = 1.f / (1.f + expf(-(xz2.y + bz2.y + ghz1 + cz2.y)));
                float nn0 = tanhf(xn2.x + bq2.x + rr0 * (ghn0 + cq2.x));
                float nn1 = tanhf(xn2.y + bq2.y + rr1 * (ghn1 + cq2.y));
                float h0 = (1.f - zz0) * nn0 + zz0 * hp2.x;
                float h1 = (1.f - zz1) * nn1 + zz1 * hp2.y;
                *(__half2*)(hout + (size_t)r * H_DIM + c) =
                    __floats2half2_rn(h0, h1);
            }
        }
    }
}

// ---------------------------------------------------------------------------
// GRU gate, t=0 only (h_prev = 0, gh = 0): all rows, writes h buffer A.
// ---------------------------------------------------------------------------
struct GateP {
    const __half* xp0; const __half* xp1;
    __half*       h0;  __half*       h1;
    const float* bih0; const float* bih1;
    const float* bhh0; const float* bhh1;
    int Bn;
};

__global__ void gru_gate0(GateP p)
{
    const int dir = blockIdx.z;
    const int gi  = blockIdx.x * blockDim.x + threadIdx.x;
    const int i   = gi >> 7;
    const int j   = (gi & 127) * 4;

    const __half* xp = (dir ? p.xp1 : p.xp0) + (size_t)i * G3 + j;
    float4 xr = ldh4(xp);
    float4 xz = ldh4(xp + 512);
    float4 xn = ldh4(xp + 1024);

    const float* bih = (dir ? p.bih1 : p.bih0) + j;
    const float* bhh = (dir ? p.bhh1 : p.bhh0) + j;
    float4 br = *(const float4*)(bih);
    float4 bz = *(const float4*)(bih + 512);
    float4 bq = *(const float4*)(bih + 1024);
    float4 cr = *(const float4*)(bhh);
    float4 cz = *(const float4*)(bhh + 512);
    float4 cq = *(const float4*)(bhh + 1024);

    __half* hp = (dir ? p.h1 : p.h0) + (size_t)i * H_DIM + j;

    float4 res;
#define GATE(c)                                                                \
    {                                                                          \
        float r = 1.f / (1.f + expf(-(xr.c + br.c + cr.c)));                   \
        float z = 1.f / (1.f + expf(-(xz.c + bz.c + cz.c)));                   \
        float n = tanhf(xn.c + bq.c + r * cq.c);                               \
        res.c = (1.f - z) * n;                                                 \
    }
    GATE(x) GATE(y) GATE(z) GATE(w)
#undef GATE
    *(__half2*)(hp)     = __floats2half2_rn(res.x, res.y);
    *(__half2*)(hp + 2) = __floats2half2_rn(res.z, res.w);
}

// ---------------------------------------------------------------------------
// Launch sequence (graph-capturable; side stream for gather t=1..7)
// ---------------------------------------------------------------------------
extern "C" void kernel_launch(void* const* d_in, const int* in_sizes, int n_in,
                              void* d_out, int out_size)
{
    const float* win   = (const float*)d_in[0];
    const int*   wlen  = (const int*)  d_in[1];
    const float* Wih_f = (const float*)d_in[2];
    const float* Whh_f = (const float*)d_in[3];
    const float* bih_f = (const float*)d_in[4];
    const float* bhh_f = (const float*)d_in[5];
    const float* Wih_b = (const float*)d_in[6];
    const float* Whh_b = (const float*)d_in[7];
    const float* bih_b = (const float*)d_in[8];
    const float* bhh_b = (const float*)d_in[9];
    const float* W1    = (const float*)d_in[10];
    const float* b1    = (const float*)d_in[11];
    const float* W2    = (const float*)d_in[12];
    const float* b2    = (const float*)d_in[13];
    float* out = (float*)d_out;

    const int Bn = in_sizes[1];

    __half *xp0, *xp1, *h0a, *h0b, *h1a, *h1b, *hid, *winh, *wh;
    int *perm, *lenf_s, *lenb_s, *nt;
    cudaGetSymbolAddress((void**)&xp0,    g_xp0);
    cudaGetSymbolAddress((void**)&xp1,    g_xp1);
    cudaGetSymbolAddress((void**)&h0a,    g_h0a);
    cudaGetSymbolAddress((void**)&h0b,    g_h0b);
    cudaGetSymbolAddress((void**)&h1a,    g_h1a);
    cudaGetSymbolAddress((void**)&h1b,    g_h1b);
    cudaGetSymbolAddress((void**)&hid,    g_hid);
    cudaGetSymbolAddress((void**)&winh,   g_winh);
    cudaGetSymbolAddress((void**)&wh,     g_wh);
    cudaGetSymbolAddress((void**)&perm,   g_perm);
    cudaGetSymbolAddress((void**)&lenf_s, g_lenf_s);
    cudaGetSymbolAddress((void**)&lenb_s, g_lenb_s);
    cudaGetSymbolAddress((void**)&nt,     g_nt);

    static bool init_done = false;
    static cudaStream_t s2;
    static cudaEvent_t  eFork;
    static cudaEvent_t  eT[MAXL];
    if (!init_done) {
        cudaFuncSetAttribute(gemm_f16<MODE_GATHER, EPI_NONE, 1>,
                             cudaFuncAttributeMaxDynamicSharedMemorySize, SMEM_REQ);
        cudaFuncSetAttribute(gemm_f16<MODE_CONCAT, EPI_BIAS_RELU, 1>,
                             cudaFuncAttributeMaxDynamicSharedMemorySize, SMEM_REQ);
        cudaFuncSetAttribute(gemm_f16<MODE_PLAIN, EPI_BIAS, 0>,
                             cudaFuncAttributeMaxDynamicSharedMemorySize, SMEM_REQ);
        cudaFuncSetAttribute(gemm_rec_fused,
                             cudaFuncAttributeMaxDynamicSharedMemorySize, SMEM_REQ);
        cudaStreamCreateWithFlags(&s2, cudaStreamNonBlocking);
        cudaEventCreateWithFlags(&eFork, cudaEventDisableTiming);
        for (int t = 0; t < MAXL; ++t)
            cudaEventCreateWithFlags(&eT[t], cudaEventDisableTiming);
        init_done = true;
    }

    // --- 0a) Converts (main stream) ---
    {
        win2half<<<Bn * T_WIN, 128>>>((const float4*)win, (uint2*)winh, wlen);

        W6 w;
        w.src[0] = (const float4*)Wih_f; w.dst[0] = (uint4*)(wh + WH_WIHF);
        w.src[1] = (const float4*)Whh_f; w.dst[1] = (uint4*)(wh + WH_WHHF);
        w.src[2] = (const float4*)Wih_b; w.dst[2] = (uint4*)(wh + WH_WIHB);
        w.src[3] = (const float4*)Whh_b; w.dst[3] = (uint4*)(wh + WH_WHHB);
        w.src[4] = (const float4*)W1;    w.dst[4] = (uint4*)(wh + WH_W1);
        w.src[5] = (const float4*)W2;    w.dst[5] = (uint4*)(wh + WH_W2);
        w.n8[0] = w.n8[1] = w.n8[2] = w.n8[3] = G3 * D_DIM / 8;
        w.n8[4] = H_DIM * 2 * H_DIM / 8;
        w.n8[5] = H_DIM * H_DIM / 8;
        const int tot = 4 * (G3 * D_DIM / 8) + H_DIM * 2 * H_DIM / 8
                      + H_DIM * H_DIM / 8;
        weights2half<<<(tot + 255) / 256, 256>>>(w);
    }

    // --- 0b) Sort (main stream) ---
    const int nchunks = Bn / 256;
    sort1<<<nchunks, 256>>>(wlen);
    sort2<<<1, 32>>>(nchunks);
    sort3<<<nchunks, 256>>>(wlen);

    // --- fork side stream ---
    cudaEventRecord(eFork, 0);
    cudaStreamWaitEvent(s2, eFork, 0);

    // --- 1) Per-timestep gather GEMMs ---
    GemmP p1 = {};
    p1.win = winh;
    p1.B0 = wh + WH_WIHF; p1.B1 = wh + WH_WIHB;
    p1.perm = perm; p1.lenf_s = lenf_s; p1.lenb_s = lenb_s; p1.nt = nt;
    p1.M = Bn; p1.N = G3; p1.K = D_DIM; p1.Bn = Bn;

    const dim3 ggrid_gemm(G3 / 128, Bn / 128, 2);

    p1.step = 0;
    p1.C0 = xp0; p1.C1 = xp1;
    gemm_f16<MODE_GATHER, EPI_NONE, 1>
        <<<ggrid_gemm, 256, SMEM_REQ>>>(p1);

    for (int t = 1; t < MAXL; ++t) {
        p1.step = t;
        p1.C0 = xp0 + (size_t)t * Bn * G3;
        p1.C1 = xp1 + (size_t)t * Bn * G3;
        gemm_f16<MODE_GATHER, EPI_NONE, 1>
            <<<ggrid_gemm, 256, SMEM_REQ, s2>>>(p1);
        cudaEventRecord(eT[t], s2);
    }

    // --- 2) t=0 gate, then fused GEMM+gate for t=1..7 ---
    GateP gp;
    gp.xp0 = xp0; gp.xp1 = xp1;
    gp.h0 = h0a;  gp.h1 = h1a;
    gp.bih0 = bih_f; gp.bih1 = bih_b;
    gp.bhh0 = bhh_f; gp.bhh1 = bhh_b;
    gp.Bn = Bn;
    gru_gate0<<<dim3((Bn * (H_DIM / 4)) / 256, 1, 2), 256>>>(gp);

    FuseP fp = {};
    fp.W0 = wh + WH_WHHF; fp.W1 = wh + WH_WHHB;
    fp.xp0 = xp0; fp.xp1 = xp1;
    fp.bih0 = bih_f; fp.bih1 = bih_b;
    fp.bhh0 = bhh_f; fp.bhh1 = bhh_b;
    fp.nt = nt; fp.Bn = Bn;
    for (int t = 1; t < MAXL; ++t) {
        const bool in_a = ((t - 1) & 1) == 0;
        fp.hin0  = in_a ? h0a : h0b;
        fp.hin1  = in_a ? h1a : h1b;
        fp.hout0 = in_a ? h0b : h0a;
        fp.hout1 = in_a ? h1b : h1a;
        fp.t = t;
        cudaStreamWaitEvent(0, eT[t], 0);   // xp[t] ready (epilogue reads it)
        gemm_rec_fused<<<dim3(H_DIM / 64, Bn / 64, 2), 256, SMEM_REQ>>>(fp);
    }

    // --- 3) MLP (per-row h parity select), final GEMM scatters ---
    GemmP p3 = {};
    p3.A0 = h0a; p3.A0b = h0b;
    p3.A1 = h1a; p3.A1b = h1b;
    p3.B0 = wh + WH_W1; p3.B1 = wh + WH_W1;
    p3.C0 = hid; p3.C1 = hid;
    p3.bias = b1;
    p3.lenf_s = lenf_s; p3.lenb_s = lenb_s;
    p3.M = Bn; p3.N = H_DIM; p3.K = 2 * H_DIM; p3.Bn = Bn;
    gemm_f16<MODE_CONCAT, EPI_BIAS_RELU, 1>
        <<<dim3(H_DIM / 128, Bn / 128, 1), 256, SMEM_REQ>>>(p3);

    GemmP p4 = {};
    p4.A0 = hid; p4.A1 = hid;
    p4.B0 = wh + WH_W2; p4.B1 = wh + WH_W2;
    p4.C0 = out; p4.C1 = out;
    p4.bias = b2;
    p4.operm = perm;
    p4.M = Bn; p4.N = H_DIM; p4.K = H_DIM; p4.Bn = Bn;
    gemm_f16<MODE_PLAIN, EPI_BIAS, 0>
        <<<dim3(H_DIM / 128, Bn / 128, 1), 256, SMEM_REQ>>>(p4);
}

// round 13
// speedup vs baseline: 1.1285x; 1.1285x over previous
#include <cuda_runtime.h>
#include <cuda_fp16.h>
#include <math.h>
#include <cstdint>

// ---------------------------------------------------------------------------
// Problem constants: B=8192, T=15, D=H=512, MAXL=8, CENTER=7
// ---------------------------------------------------------------------------
#define B_MAX   8192
#define T_WIN   15
#define D_DIM   512
#define H_DIM   512
#define G3      1536
#define MAXL    8

#define PITCH_H      40                    // smem row pitch in halfs (80 B)
#define STAGES       4                     // K32 stages
#define STAGE_HALFS  (128 * PITCH_H)       // 5120 halfs = 10240 B
#define SMEM_REQ     (STAGES * STAGE_HALFS * 2 * 2)   // 81920 B

// ---------------------------------------------------------------------------
// Scratch (all GEMM-facing intermediates in fp16)
// ---------------------------------------------------------------------------
__device__ __half g_xp0[B_MAX * MAXL * G3];   // [t][sorted_i][1536] fwd
__device__ __half g_xp1[B_MAX * MAXL * G3];
__device__ __half g_gh0[B_MAX * G3];          // h@Whh^T
__device__ __half g_gh1[B_MAX * G3];
__device__ __half g_h0 [B_MAX * H_DIM];       // hidden states (sorted)
__device__ __half g_h1 [B_MAX * H_DIM];
__device__ __half g_hid[B_MAX * H_DIM];       // MLP hidden
__device__ __half g_winh[B_MAX * T_WIN * D_DIM];  // fp16 window (masked)
#define WH_WIHF 0
#define WH_WHHF (G3 * D_DIM)
#define WH_WIHB (2 * G3 * D_DIM)
#define WH_WHHB (3 * G3 * D_DIM)
#define WH_W1   (4 * G3 * D_DIM)
#define WH_W2   (4 * G3 * D_DIM + H_DIM * 2 * H_DIM)
__device__ __half g_wh[4 * G3 * D_DIM + H_DIM * 2 * H_DIM + H_DIM * H_DIM];

// ---- length-compaction state ----
#define MAX_CHUNKS 64
__device__ int g_chunk_hist[MAX_CHUNKS][16];
__device__ int g_chunk_base[MAX_CHUNKS][16];
__device__ int g_lrank [B_MAX];
__device__ int g_perm  [B_MAX];
__device__ int g_lenf_s[B_MAX];
__device__ int g_lenb_s[B_MAX];
__device__ int g_nt[2 * MAXL];

// ---------------------------------------------------------------------------
// PTX helpers
// ---------------------------------------------------------------------------
__device__ __forceinline__ void ldsm4(unsigned* r, const __half* p) {
    unsigned addr = (unsigned)__cvta_generic_to_shared(p);
    asm volatile("ldmatrix.sync.aligned.m8n8.x4.shared.b16 {%0,%1,%2,%3}, [%4];"
                 : "=r"(r[0]), "=r"(r[1]), "=r"(r[2]), "=r"(r[3]) : "r"(addr));
}

__device__ __forceinline__ void mma_f16(float* c, const unsigned* a,
                                        unsigned b0, unsigned b1) {
    asm volatile(
        "mma.sync.aligned.m16n8k16.row.col.f32.f16.f16.f32 "
        "{%0,%1,%2,%3}, {%4,%5,%6,%7}, {%8,%9}, {%0,%1,%2,%3};"
        : "+f"(c[0]), "+f"(c[1]), "+f"(c[2]), "+f"(c[3])
        : "r"(a[0]), "r"(a[1]), "r"(a[2]), "r"(a[3]), "r"(b0), "r"(b1));
}

__device__ __forceinline__ void cpasync16(void* sp, const void* gp) {
    unsigned sa = (unsigned)__cvta_generic_to_shared(sp);
    asm volatile("cp.async.cg.shared.global [%0], [%1], 16;"
                 :: "r"(sa), "l"(gp) : "memory");
}
#define CP_COMMIT() asm volatile("cp.async.commit_group;" ::: "memory")
#define CP_WAIT(N)  asm volatile("cp.async.wait_group %0;" :: "n"(N) : "memory")

__device__ __forceinline__ float4 ldh4(const __half* p) {
    __half2 a = *(const __half2*)(p);
    __half2 b = *(const __half2*)(p + 2);
    float2 fa = __half22float2(a);
    float2 fb = __half22float2(b);
    return make_float4(fa.x, fa.y, fb.x, fb.y);
}

// ---------------------------------------------------------------------------
// Masked window convert: only rows the gather reads (pos in [8-lf, 6+lb])
// ---------------------------------------------------------------------------
__global__ void win2half(const float4* __restrict__ win,
                         uint2* __restrict__ dst,
                         const int* __restrict__ wlen) {
    const int row = blockIdx.x;              // b*15 + pos
    const int b   = row / T_WIN;
    const int pos = row % T_WIN;
    const int wl  = wlen[b];
    const int lo  = 7 - (wl - 1) / 2;
    const int hi  = 7 + wl / 2;
    if (pos < lo || pos > hi) return;
    const int tid = threadIdx.x;             // 128 thr x 4 elems = 512
    float4 v = win[(size_t)row * 128 + tid];
    __half2 h0 = __floats2half2_rn(v.x, v.y);
    __half2 h1 = __floats2half2_rn(v.z, v.w);
    uint2 o;
    o.x = *(unsigned*)&h0; o.y = *(unsigned*)&h1;
    dst[(size_t)row * 128 + tid] = o;
}

// ---------------------------------------------------------------------------
// All 6 weight matrices converted in ONE launch (segment-indexed)
// ---------------------------------------------------------------------------
struct W6 {
    const float4* src[6];
    uint4*        dst[6];
    int           n8[6];
};

__global__ void weights2half(W6 w) {
    int i = blockIdx.x * blockDim.x + threadIdx.x;
    #pragma unroll
    for (int s = 0; s < 6; ++s) {
        if (i < w.n8[s]) {
            float4 a = w.src[s][2 * i], b = w.src[s][2 * i + 1];
            __half2 h0 = __floats2half2_rn(a.x, a.y);
            __half2 h1 = __floats2half2_rn(a.z, a.w);
            __half2 h2 = __floats2half2_rn(b.x, b.y);
            __half2 h3 = __floats2half2_rn(b.z, b.w);
            uint4 o;
            o.x = *(unsigned*)&h0; o.y = *(unsigned*)&h1;
            o.z = *(unsigned*)&h2; o.w = *(unsigned*)&h3;
            w.dst[s][i] = o;
            return;
        }
        i -= w.n8[s];
    }
}

// ---------------------------------------------------------------------------
// Deterministic counting sort by window_len descending
// ---------------------------------------------------------------------------
__global__ void sort1(const int* __restrict__ wlen) {
    __shared__ int s_wl[256];
    __shared__ int s_rank[256];
    __shared__ int s_h[16];
    const int c = blockIdx.x, tid = threadIdx.x;
    s_wl[tid] = wlen[c * 256 + tid];
    if (tid < 16) s_h[tid] = 0;
    __syncthreads();
    if (tid == 0) {
        #pragma unroll 4
        for (int k = 0; k < 256; ++k) { int w = s_wl[k]; s_rank[k] = s_h[w]++; }
    }
    __syncthreads();
    g_lrank[c * 256 + tid] = s_rank[tid];
    if (tid < 16) g_chunk_hist[c][tid] = s_h[tid];
}

__global__ void sort2(int nchunks) {
    const int tid = threadIdx.x;   // 32 threads
    __shared__ int total[16];
    __shared__ int wbase[16];
    if (tid < 16) {
        int s = 0;
        #pragma unroll 8
        for (int c = 0; c < nchunks; ++c) s += g_chunk_hist[c][tid];
        total[tid] = s;
    }
    __syncthreads();
    if (tid == 0) {
        int off = 0;
        for (int w = 15; w >= 1; --w) { wbase[w] = off; off += total[w]; }
    }
    __syncthreads();
    if (tid >= 1 && tid <= 15) {
        int run = wbase[tid];
        for (int c = 0; c < nchunks; ++c) {
            g_chunk_base[c][tid] = run;
            run += g_chunk_hist[c][tid];
        }
    }
    if (tid < MAXL) {
        int nf = 0, nb = 0;
        #pragma unroll
        for (int w = 1; w <= 15; ++w) {
            if ((w - 1) / 2 + 1 > tid) nf += total[w];
            if (w / 2 + 1 > tid)       nb += total[w];
        }
        g_nt[tid]        = nf;
        g_nt[MAXL + tid] = nb;
    }
}

__global__ void sort3(const int* __restrict__ wlen) {
    const int c = blockIdx.x;
    const int i = c * 256 + threadIdx.x;
    const int w = wlen[i];
    const int pos = g_chunk_base[c][w] + g_lrank[i];
    g_perm[pos]   = i;
    g_lenf_s[pos] = (w - 1) / 2 + 1;
    g_lenb_s[pos] = w / 2 + 1;
}

// ---------------------------------------------------------------------------
// fp16 tensor-core NT GEMM: C[M,N] = A[M,K] @ B[N,K]^T  (fp32 accum)
// GATHER mode is per-timestep (p.step = t, C pre-offset to t's block).
// ---------------------------------------------------------------------------
enum { MODE_GATHER = 0, MODE_PLAIN = 1, MODE_CONCAT = 2 };
enum { EPI_NONE = 0, EPI_BIAS = 1, EPI_BIAS_RELU = 2 };

struct GemmP {
    const __half* A0;
    const __half* A1;
    const __half* B0;
    const __half* B1;
    void*         C0;
    void*         C1;
    const __half* win;
    const float*  bias;
    const int*    perm;
    const int*    lenf_s;
    const int*    lenb_s;
    const int*    nt;
    const int*    operm;
    int M, N, K, step, Bn;
};

template<int MODE, int EPI, int OUTH>
__global__ __launch_bounds__(256, 2)
void gemm_f16(GemmP p)
{
    const int dir = blockIdx.z;
    const int bm  = blockIdx.y;
    const int bn  = blockIdx.x;

    // ---- length-compaction early exit ----
    if (MODE == MODE_GATHER) {
        if (bm * 128 >= p.nt[dir * MAXL + p.step]) return;
    } else if (p.nt) {
        if (bm * 128 >= p.nt[dir * MAXL + p.step]) return;
    }

    extern __shared__ __half hsm[];
    __half* As = hsm;
    __half* Bs = hsm + STAGES * STAGE_HALFS;

    const __half* __restrict__ Bmat = dir ? p.B1 : p.B0;
    const int K = p.K;
    const int N = p.N;

    const int tid  = threadIdx.x;
    const int warp = tid >> 5;
    const int lane = tid & 31;
    const int wm   = (warp >> 1) * 32;
    const int wn   = (warp & 1) * 64;

    const int lr = tid >> 2;
    const int lc = (tid & 3) * 8;

    const __half* arow0 = nullptr;
    const __half* arow1 = nullptr;
    const __half* ab0 = nullptr;
    const __half* ab1 = nullptr;

    if (MODE == MODE_GATHER) {
        const int t = p.step;
        #pragma unroll
        for (int q = 0; q < 2; ++q) {
            const int i   = bm * 128 + lr + q * 64;
            const int b   = p.perm[i];
            const int len = dir ? p.lenb_s[i] : p.lenf_s[i];
            int idx = dir ? (6 + len - t) : (8 - len + t);
            idx = min(max(idx, 0), T_WIN - 1);
            const __half* rp = p.win + ((size_t)b * T_WIN + idx) * D_DIM;
            if (q == 0) arow0 = rp; else arow1 = rp;
        }
    } else if (MODE == MODE_PLAIN) {
        arow0 = (dir ? p.A1 : p.A0) + (size_t)(bm * 128 + lr) * K;
        arow1 = arow0 + (size_t)64 * K;
    } else {
        const int r0 = bm * 128 + lr;
        arow0 = p.A0 + (size_t)r0 * 512;
        arow1 = p.A0 + (size_t)(r0 + 64) * 512;
        ab0   = p.A1 + (size_t)r0 * 512;
        ab1   = p.A1 + (size_t)(r0 + 64) * 512;
    }

    const __half* brow0 = Bmat + (size_t)(bn * 128 + lr) * K;
    const __half* brow1 = brow0 + (size_t)64 * K;

    float acc[2][8][4];
    #pragma unroll
    for (int i = 0; i < 2; ++i)
        #pragma unroll
        for (int t = 0; t < 8; ++t)
            #pragma unroll
            for (int v = 0; v < 4; ++v) acc[i][t][v] = 0.f;

    const int KT = K >> 5;

#define LOAD_STAGE(S, KI)                                                      \
    do {                                                                       \
        if ((KI) < KT) {                                                       \
            const int K0 = (KI) * 32;                                          \
            __half* da = As + (S) * STAGE_HALFS + lr * PITCH_H + lc;           \
            __half* db = Bs + (S) * STAGE_HALFS + lr * PITCH_H + lc;           \
            const __half *pa0, *pa1;                                           \
            if (MODE == MODE_CONCAT) {                                         \
                pa0 = ((K0 < 512) ? arow0 : ab0) + (K0 & 511) + lc;            \
                pa1 = ((K0 < 512) ? arow1 : ab1) + (K0 & 511) + lc;            \
            } else {                                                           \
                pa0 = arow0 + K0 + lc;                                         \
                pa1 = arow1 + K0 + lc;                                         \
            }                                                                  \
            cpasync16(da,                pa0);                                 \
            cpasync16(da + 64 * PITCH_H, pa1);                                 \
            cpasync16(db,                brow0 + K0 + lc);                     \
            cpasync16(db + 64 * PITCH_H, brow1 + K0 + lc);                     \
        }                                                                      \
        CP_COMMIT();                                                           \
    } while (0)

    #pragma unroll
    for (int s = 0; s < STAGES - 1; ++s) LOAD_STAGE(s, s);

    for (int kt = 0; kt < KT; ++kt) {
        CP_WAIT(STAGES - 2);
        __syncthreads();

        const int buf = kt & (STAGES - 1);
        const __half* Ab = As + buf * STAGE_HALFS;
        const __half* Bb = Bs + buf * STAGE_HALFS;

        #pragma unroll
        for (int ks = 0; ks < 2; ++ks) {
            const int k0 = ks * 16;
            unsigned a[2][4];
            #pragma unroll
            for (int i = 0; i < 2; ++i)
                ldsm4(a[i], Ab + (wm + i * 16 + (lane & 15)) * PITCH_H
                               + k0 + (lane >> 4) * 8);
            unsigned b[4][4];
            #pragma unroll
            for (int t4 = 0; t4 < 4; ++t4)
                ldsm4(b[t4], Bb + (wn + t4 * 16 + ((lane >> 4) << 3)
                                   + (lane & 7)) * PITCH_H
                                + k0 + ((lane >> 3) & 1) * 8);
            #pragma unroll
            for (int i = 0; i < 2; ++i)
                #pragma unroll
                for (int t4 = 0; t4 < 4; ++t4) {
                    mma_f16(acc[i][2 * t4],     a[i], b[t4][0], b[t4][1]);
                    mma_f16(acc[i][2 * t4 + 1], a[i], b[t4][2], b[t4][3]);
                }
        }

        LOAD_STAGE((kt + STAGES - 1) & (STAGES - 1), kt + STAGES - 1);
    }
#undef LOAD_STAGE

    // ---- epilogue ----
    const int qr = lane >> 2;
    const int qc = (lane & 3) * 2;
    #pragma unroll
    for (int i = 0; i < 2; ++i) {
        const int rA = bm * 128 + wm + i * 16 + qr;
        const int gA = p.operm ? p.operm[rA]     : rA;
        const int gB = p.operm ? p.operm[rA + 8] : rA + 8;
        #pragma unroll
        for (int t = 0; t < 8; ++t) {
            const int cc = bn * 128 + wn + t * 8 + qc;
            float v0 = acc[i][t][0], v1 = acc[i][t][1];
            float v2 = acc[i][t][2], v3 = acc[i][t][3];
            if (EPI != EPI_NONE) {
                float b0 = p.bias[cc], b1 = p.bias[cc + 1];
                v0 += b0; v1 += b1; v2 += b0; v3 += b1;
                if (EPI == EPI_BIAS_RELU) {
                    v0 = fmaxf(v0, 0.f); v1 = fmaxf(v1, 0.f);
                    v2 = fmaxf(v2, 0.f); v3 = fmaxf(v3, 0.f);
                }
            }
            if (OUTH) {
                __half* Ch = (__half*)(dir ? p.C1 : p.C0);
                *(__half2*)(Ch + (size_t)gA * N + cc) = __floats2half2_rn(v0, v1);
                *(__half2*)(Ch + (size_t)gB * N + cc) = __floats2half2_rn(v2, v3);
            } else {
                float* Cf = (float*)(dir ? p.C1 : p.C0);
                *(float2*)(Cf + (size_t)gA * N + cc) = make_float2(v0, v1);
                *(float2*)(Cf + (size_t)gB * N + cc) = make_float2(v2, v3);
            }
        }
    }
}

// ---------------------------------------------------------------------------
// GRU gate update on sorted rows (prefix-active). xp/gh/h all fp16.
// ---------------------------------------------------------------------------
struct GateP {
    const __half* xp0; const __half* xp1;
    const __half* gh0; const __half* gh1;
    __half*       h0;  __half*       h1;
    const float* bih0; const float* bih1;
    const float* bhh0; const float* bhh1;
    const int*   nt;
    int t, Bn;
};

__global__ void gru_gate(GateP p)
{
    const int dir = blockIdx.z;
    const int gi  = blockIdx.x * blockDim.x + threadIdx.x;
    const int i   = gi >> 7;
    const int j   = (gi & 127) * 4;
    const int t   = p.t;

    if (i >= p.nt[dir * MAXL + t]) return;

    const __half* xp = (dir ? p.xp1 : p.xp0)
                     + ((size_t)t * p.Bn + i) * G3 + j;
    float4 xr = ldh4(xp);
    float4 xz = ldh4(xp + 512);
    float4 xn = ldh4(xp + 1024);

    const float* bih = (dir ? p.bih1 : p.bih0) + j;
    const float* bhh = (dir ? p.bhh1 : p.bhh0) + j;
    float4 br = *(const float4*)(bih);
    float4 bz = *(const float4*)(bih + 512);
    float4 bq = *(const float4*)(bih + 1024);
    float4 cr = *(const float4*)(bhh);
    float4 cz = *(const float4*)(bhh + 512);
    float4 cq = *(const float4*)(bhh + 1024);

    __half* hp = (dir ? p.h1 : p.h0) + (size_t)i * H_DIM + j;
    float4 hr, hz, hq, hv;
    if (t > 0) {
        const __half* gh = (dir ? p.gh1 : p.gh0) + (size_t)i * G3 + j;
        hr = ldh4(gh);
        hz = ldh4(gh + 512);
        hq = ldh4(gh + 1024);
        hv = ldh4(hp);
    } else {
        hr = hz = hq = make_float4(0.f, 0.f, 0.f, 0.f);
        hv = make_float4(0.f, 0.f, 0.f, 0.f);
    }

    float4 res;
#define GATE(c)                                                                \
    {                                                                          \
        float r = 1.f / (1.f + expf(-(xr.c + br.c + hr.c + cr.c)));            \
        float z = 1.f / (1.f + expf(-(xz.c + bz.c + hz.c + cz.c)));            \
        float n = tanhf(xn.c + bq.c + r * (hq.c + cq.c));                      \
        res.c = (1.f - z) * n + z * hv.c;                                      \
    }
    GATE(x) GATE(y) GATE(z) GATE(w)
#undef GATE
    *(__half2*)(hp)     = __floats2half2_rn(res.x, res.y);
    *(__half2*)(hp + 2) = __floats2half2_rn(res.z, res.w);
}

// ---------------------------------------------------------------------------
// Launch sequence (graph-capturable; two forked side chains)
// ---------------------------------------------------------------------------
extern "C" void kernel_launch(void* const* d_in, const int* in_sizes, int n_in,
                              void* d_out, int out_size)
{
    const float* win   = (const float*)d_in[0];
    const int*   wlen  = (const int*)  d_in[1];
    const float* Wih_f = (const float*)d_in[2];
    const float* Whh_f = (const float*)d_in[3];
    const float* bih_f = (const float*)d_in[4];
    const float* bhh_f = (const float*)d_in[5];
    const float* Wih_b = (const float*)d_in[6];
    const float* Whh_b = (const float*)d_in[7];
    const float* bih_b = (const float*)d_in[8];
    const float* bhh_b = (const float*)d_in[9];
    const float* W1    = (const float*)d_in[10];
    const float* b1    = (const float*)d_in[11];
    const float* W2    = (const float*)d_in[12];
    const float* b2    = (const float*)d_in[13];
    float* out = (float*)d_out;

    const int Bn = in_sizes[1];

    __half *xp0, *xp1, *gh0, *gh1, *h0, *h1, *hid, *winh, *wh;
    int *perm, *lenf_s, *lenb_s, *nt;
    cudaGetSymbolAddress((void**)&xp0,    g_xp0);
    cudaGetSymbolAddress((void**)&xp1,    g_xp1);
    cudaGetSymbolAddress((void**)&gh0,    g_gh0);
    cudaGetSymbolAddress((void**)&gh1,    g_gh1);
    cudaGetSymbolAddress((void**)&h0,     g_h0);
    cudaGetSymbolAddress((void**)&h1,     g_h1);
    cudaGetSymbolAddress((void**)&hid,    g_hid);
    cudaGetSymbolAddress((void**)&winh,   g_winh);
    cudaGetSymbolAddress((void**)&wh,     g_wh);
    cudaGetSymbolAddress((void**)&perm,   g_perm);
    cudaGetSymbolAddress((void**)&lenf_s, g_lenf_s);
    cudaGetSymbolAddress((void**)&lenb_s, g_lenb_s);
    cudaGetSymbolAddress((void**)&nt,     g_nt);

    static bool init_done = false;
    static cudaStream_t s2;
    static cudaEvent_t  eFork, eWin, ePre;
    static cudaEvent_t  eT[MAXL];
    if (!init_done) {
        cudaFuncSetAttribute(gemm_f16<MODE_GATHER, EPI_NONE, 1>,
                             cudaFuncAttributeMaxDynamicSharedMemorySize, SMEM_REQ);
        cudaFuncSetAttribute(gemm_f16<MODE_PLAIN, EPI_NONE, 1>,
                             cudaFuncAttributeMaxDynamicSharedMemorySize, SMEM_REQ);
        cudaFuncSetAttribute(gemm_f16<MODE_CONCAT, EPI_BIAS_RELU, 1>,
                             cudaFuncAttributeMaxDynamicSharedMemorySize, SMEM_REQ);
        cudaFuncSetAttribute(gemm_f16<MODE_PLAIN, EPI_BIAS, 0>,
                             cudaFuncAttributeMaxDynamicSharedMemorySize, SMEM_REQ);
        cudaStreamCreateWithFlags(&s2, cudaStreamNonBlocking);
        cudaEventCreateWithFlags(&eFork, cudaEventDisableTiming);
        cudaEventCreateWithFlags(&eWin,  cudaEventDisableTiming);
        cudaEventCreateWithFlags(&ePre,  cudaEventDisableTiming);
        for (int t = 0; t < MAXL; ++t)
            cudaEventCreateWithFlags(&eT[t], cudaEventDisableTiming);
        init_done = true;
    }

    // --- fork at entry: side chain does weights-convert + sort ---
    cudaEventRecord(eFork, 0);
    cudaStreamWaitEvent(s2, eFork, 0);

    // side chain (s2): weights2half -> sort1/2/3 -> ePre
    {
        W6 w;
        w.src[0] = (const float4*)Wih_f; w.dst[0] = (uint4*)(wh + WH_WIHF);
        w.src[1] = (const float4*)Whh_f; w.dst[1] = (uint4*)(wh + WH_WHHF);
        w.src[2] = (const float4*)Wih_b; w.dst[2] = (uint4*)(wh + WH_WIHB);
        w.src[3] = (const float4*)Whh_b; w.dst[3] = (uint4*)(wh + WH_WHHB);
        w.src[4] = (const float4*)W1;    w.dst[4] = (uint4*)(wh + WH_W1);
        w.src[5] = (const float4*)W2;    w.dst[5] = (uint4*)(wh + WH_W2);
        w.n8[0] = w.n8[1] = w.n8[2] = w.n8[3] = G3 * D_DIM / 8;
        w.n8[4] = H_DIM * 2 * H_DIM / 8;
        w.n8[5] = H_DIM * H_DIM / 8;
        const int tot = 4 * (G3 * D_DIM / 8) + H_DIM * 2 * H_DIM / 8
                      + H_DIM * H_DIM / 8;
        weights2half<<<(tot + 255) / 256, 256, 0, s2>>>(w);
    }
    const int nchunks = Bn / 256;
    sort1<<<nchunks, 256, 0, s2>>>(wlen);
    sort2<<<1, 32, 0, s2>>>(nchunks);
    sort3<<<nchunks, 256, 0, s2>>>(wlen);
    cudaEventRecord(ePre, s2);

    // main chain: window convert -> eWin
    win2half<<<Bn * T_WIN, 128>>>((const float4*)win, (uint2*)winh, wlen);
    cudaEventRecord(eWin, 0);

    // --- 1) Per-timestep gather GEMMs ---
    GemmP p1 = {};
    p1.win = winh;
    p1.B0 = wh + WH_WIHF; p1.B1 = wh + WH_WIHB;
    p1.perm = perm; p1.lenf_s = lenf_s; p1.lenb_s = lenb_s; p1.nt = nt;
    p1.M = Bn; p1.N = G3; p1.K = D_DIM; p1.Bn = Bn;

    const dim3 ggrid_gemm(G3 / 128, Bn / 128, 2);

    // t=0 on main stream (needs wh/perm/nt from side chain)
    cudaStreamWaitEvent(0, ePre, 0);
    p1.step = 0;
    p1.C0 = xp0; p1.C1 = xp1;
    gemm_f16<MODE_GATHER, EPI_NONE, 1>
        <<<ggrid_gemm, 256, SMEM_REQ>>>(p1);

    // t=1..7 on side stream (needs winh from main chain)
    cudaStreamWaitEvent(s2, eWin, 0);
    for (int t = 1; t < MAXL; ++t) {
        p1.step = t;
        p1.C0 = xp0 + (size_t)t * Bn * G3;
        p1.C1 = xp1 + (size_t)t * Bn * G3;
        gemm_f16<MODE_GATHER, EPI_NONE, 1>
            <<<ggrid_gemm, 256, SMEM_REQ, s2>>>(p1);
        cudaEventRecord(eT[t], s2);
    }

    // --- 2) Recurrence chain on main stream ---
    GateP gp;
    gp.xp0 = xp0; gp.xp1 = xp1;
    gp.gh0 = gh0; gp.gh1 = gh1;
    gp.h0  = h0;  gp.h1  = h1;
    gp.bih0 = bih_f; gp.bih1 = bih_b;
    gp.bhh0 = bhh_f; gp.bhh1 = bhh_b;
    gp.nt = nt; gp.Bn = Bn;

    const dim3 ggrid((Bn * (H_DIM / 4)) / 256, 1, 2);
    gp.t = 0;
    gru_gate<<<ggrid, 256>>>(gp);

    GemmP p2 = {};
    p2.A0 = h0; p2.A1 = h1;
    p2.B0 = wh + WH_WHHF; p2.B1 = wh + WH_WHHB;
    p2.C0 = gh0;          p2.C1 = gh1;
    p2.nt = nt;
    p2.M = Bn; p2.N = G3; p2.K = H_DIM; p2.Bn = Bn;
    for (int t = 1; t < MAXL; ++t) {
        p2.step = t;
        gemm_f16<MODE_PLAIN, EPI_NONE, 1>
            <<<dim3(G3 / 128, Bn / 128, 2), 256, SMEM_REQ>>>(p2);
        cudaStreamWaitEvent(0, eT[t], 0);   // xp[t] ready (joins side stream)
        gp.t = t;
        gru_gate<<<ggrid, 256>>>(gp);
    }

    // --- 3) MLP (main stream; side stream fully joined via eT[7]) ---
    GemmP p3 = {};
    p3.A0 = h0; p3.A1 = h1;
    p3.B0 = wh + WH_W1; p3.B1 = wh + WH_W1;
    p3.C0 = hid; p3.C1 = hid;
    p3.bias = b1;
    p3.M = Bn; p3.N = H_DIM; p3.K = 2 * H_DIM; p3.Bn = Bn;
    gemm_f16<MODE_CONCAT, EPI_BIAS_RELU, 1>
        <<<dim3(H_DIM / 128, Bn / 128, 1), 256, SMEM_REQ>>>(p3);

    GemmP p4 = {};
    p4.A0 = hid; p4.A1 = hid;
    p4.B0 = wh + WH_W2; p4.B1 = wh + WH_W2;
    p4.C0 = out; p4.C1 = out;
    p4.bias = b2;
    p4.operm = perm;
    p4.M = Bn; p4.N = H_DIM; p4.K = H_DIM; p4.Bn = Bn;
    gemm_f16<MODE_PLAIN, EPI_BIAS, 0>
        <<<dim3(H_DIM / 128, Bn / 128, 1), 256, SMEM_REQ>>>(p4);
}

// round 14
// speedup vs baseline: 1.1533x; 1.0220x over previous
#include <cuda_runtime.h>
#include <cuda_fp16.h>
#include <math.h>
#include <cstdint>

// ---------------------------------------------------------------------------
// Problem constants: B=8192, T=15, D=H=512, MAXL=8, CENTER=7
// ---------------------------------------------------------------------------
#define B_MAX   8192
#define T_WIN   15
#define D_DIM   512
#define H_DIM   512
#define G3      1536
#define MAXL    8

#define PITCH_H      40                    // smem row pitch in halfs (80 B)
#define STAGES       4                     // K32 stages
#define STAGE_HALFS  (128 * PITCH_H)       // 5120 halfs = 10240 B
#define SMEM_REQ     (STAGES * STAGE_HALFS * 2 * 2)   // 81920 B

// ---------------------------------------------------------------------------
// Scratch (all GEMM-facing intermediates in fp16)
// ---------------------------------------------------------------------------
__device__ __half g_xp0[B_MAX * MAXL * G3];   // [t][sorted_i][1536] fwd
__device__ __half g_xp1[B_MAX * MAXL * G3];
__device__ __half g_gh0[B_MAX * G3];          // h@Whh^T
__device__ __half g_gh1[B_MAX * G3];
__device__ __half g_h0 [B_MAX * H_DIM];       // hidden states (sorted)
__device__ __half g_h1 [B_MAX * H_DIM];
__device__ __half g_hid[B_MAX * H_DIM];       // MLP hidden
__device__ __half g_winh[B_MAX * T_WIN * D_DIM];  // fp16 window (masked)
#define WH_WIHF 0
#define WH_WHHF (G3 * D_DIM)
#define WH_WIHB (2 * G3 * D_DIM)
#define WH_WHHB (3 * G3 * D_DIM)
#define WH_W1   (4 * G3 * D_DIM)
#define WH_W2   (4 * G3 * D_DIM + H_DIM * 2 * H_DIM)
__device__ __half g_wh[4 * G3 * D_DIM + H_DIM * 2 * H_DIM + H_DIM * H_DIM];

// ---- length-compaction state ----
#define MAX_CHUNKS 64
__device__ int g_chunk_hist[MAX_CHUNKS][16];
__device__ int g_chunk_base[MAX_CHUNKS][16];
__device__ int g_lrank [B_MAX];
__device__ int g_perm  [B_MAX];
__device__ int g_lenf_s[B_MAX];
__device__ int g_lenb_s[B_MAX];
__device__ int g_nt[2 * MAXL];

// ---------------------------------------------------------------------------
// PTX helpers
// ---------------------------------------------------------------------------
__device__ __forceinline__ void ldsm4(unsigned* r, const __half* p) {
    unsigned addr = (unsigned)__cvta_generic_to_shared(p);
    asm volatile("ldmatrix.sync.aligned.m8n8.x4.shared.b16 {%0,%1,%2,%3}, [%4];"
                 : "=r"(r[0]), "=r"(r[1]), "=r"(r[2]), "=r"(r[3]) : "r"(addr));
}

__device__ __forceinline__ void mma_f16(float* c, const unsigned* a,
                                        unsigned b0, unsigned b1) {
    asm volatile(
        "mma.sync.aligned.m16n8k16.row.col.f32.f16.f16.f32 "
        "{%0,%1,%2,%3}, {%4,%5,%6,%7}, {%8,%9}, {%0,%1,%2,%3};"
        : "+f"(c[0]), "+f"(c[1]), "+f"(c[2]), "+f"(c[3])
        : "r"(a[0]), "r"(a[1]), "r"(a[2]), "r"(a[3]), "r"(b0), "r"(b1));
}

__device__ __forceinline__ void cpasync16(void* sp, const void* gp) {
    unsigned sa = (unsigned)__cvta_generic_to_shared(sp);
    asm volatile("cp.async.cg.shared.global [%0], [%1], 16;"
                 :: "r"(sa), "l"(gp) : "memory");
}
#define CP_COMMIT() asm volatile("cp.async.commit_group;" ::: "memory")
#define CP_WAIT(N)  asm volatile("cp.async.wait_group %0;" :: "n"(N) : "memory")

__device__ __forceinline__ float4 ldh4(const __half* p) {
    __half2 a = *(const __half2*)(p);
    __half2 b = *(const __half2*)(p + 2);
    float2 fa = __half22float2(a);
    float2 fb = __half22float2(b);
    return make_float4(fa.x, fa.y, fb.x, fb.y);
}

// ---------------------------------------------------------------------------
// Masked window convert
// ---------------------------------------------------------------------------
__global__ void win2half(const float4* __restrict__ win,
                         uint2* __restrict__ dst,
                         const int* __restrict__ wlen) {
    const int row = blockIdx.x;
    const int b   = row / T_WIN;
    const int pos = row % T_WIN;
    const int wl  = wlen[b];
    const int lo  = 7 - (wl - 1) / 2;
    const int hi  = 7 + wl / 2;
    if (pos < lo || pos > hi) return;
    const int tid = threadIdx.x;
    float4 v = win[(size_t)row * 128 + tid];
    __half2 h0 = __floats2half2_rn(v.x, v.y);
    __half2 h1 = __floats2half2_rn(v.z, v.w);
    uint2 o;
    o.x = *(unsigned*)&h0; o.y = *(unsigned*)&h1;
    dst[(size_t)row * 128 + tid] = o;
}

// ---------------------------------------------------------------------------
// All 6 weight matrices converted in ONE launch
// ---------------------------------------------------------------------------
struct W6 {
    const float4* src[6];
    uint4*        dst[6];
    int           n8[6];
};

__global__ void weights2half(W6 w) {
    int i = blockIdx.x * blockDim.x + threadIdx.x;
    #pragma unroll
    for (int s = 0; s < 6; ++s) {
        if (i < w.n8[s]) {
            float4 a = w.src[s][2 * i], b = w.src[s][2 * i + 1];
            __half2 h0 = __floats2half2_rn(a.x, a.y);
            __half2 h1 = __floats2half2_rn(a.z, a.w);
            __half2 h2 = __floats2half2_rn(b.x, b.y);
            __half2 h3 = __floats2half2_rn(b.z, b.w);
            uint4 o;
            o.x = *(unsigned*)&h0; o.y = *(unsigned*)&h1;
            o.z = *(unsigned*)&h2; o.w = *(unsigned*)&h3;
            w.dst[s][i] = o;
            return;
        }
        i -= w.n8[s];
    }
}

// ---------------------------------------------------------------------------
// Deterministic counting sort by window_len descending
// ---------------------------------------------------------------------------
__global__ void sort1(const int* __restrict__ wlen) {
    __shared__ int s_wl[256];
    __shared__ int s_rank[256];
    __shared__ int s_h[16];
    const int c = blockIdx.x, tid = threadIdx.x;
    s_wl[tid] = wlen[c * 256 + tid];
    if (tid < 16) s_h[tid] = 0;
    __syncthreads();
    if (tid == 0) {
        #pragma unroll 4
        for (int k = 0; k < 256; ++k) { int w = s_wl[k]; s_rank[k] = s_h[w]++; }
    }
    __syncthreads();
    g_lrank[c * 256 + tid] = s_rank[tid];
    if (tid < 16) g_chunk_hist[c][tid] = s_h[tid];
}

__global__ void sort2(int nchunks) {
    const int tid = threadIdx.x;
    __shared__ int total[16];
    __shared__ int wbase[16];
    if (tid < 16) {
        int s = 0;
        #pragma unroll 8
        for (int c = 0; c < nchunks; ++c) s += g_chunk_hist[c][tid];
        total[tid] = s;
    }
    __syncthreads();
    if (tid == 0) {
        int off = 0;
        for (int w = 15; w >= 1; --w) { wbase[w] = off; off += total[w]; }
    }
    __syncthreads();
    if (tid >= 1 && tid <= 15) {
        int run = wbase[tid];
        for (int c = 0; c < nchunks; ++c) {
            g_chunk_base[c][tid] = run;
            run += g_chunk_hist[c][tid];
        }
    }
    if (tid < MAXL) {
        int nf = 0, nb = 0;
        #pragma unroll
        for (int w = 1; w <= 15; ++w) {
            if ((w - 1) / 2 + 1 > tid) nf += total[w];
            if (w / 2 + 1 > tid)       nb += total[w];
        }
        g_nt[tid]        = nf;
        g_nt[MAXL + tid] = nb;
    }
}

__global__ void sort3(const int* __restrict__ wlen) {
    const int c = blockIdx.x;
    const int i = c * 256 + threadIdx.x;
    const int w = wlen[i];
    const int pos = g_chunk_base[c][w] + g_lrank[i];
    g_perm[pos]   = i;
    g_lenf_s[pos] = (w - 1) / 2 + 1;
    g_lenb_s[pos] = w / 2 + 1;
}

// ---------------------------------------------------------------------------
// fp16 tensor-core NT GEMM: C[M,N] = A[M,K] @ B[N,K]^T  (fp32 accum)
// zdir >= 0 pins direction (single-dir launch, grid.z == 1); else blockIdx.z.
// ---------------------------------------------------------------------------
enum { MODE_GATHER = 0, MODE_PLAIN = 1, MODE_CONCAT = 2 };
enum { EPI_NONE = 0, EPI_BIAS = 1, EPI_BIAS_RELU = 2 };

struct GemmP {
    const __half* A0;
    const __half* A1;
    const __half* B0;
    const __half* B1;
    void*         C0;
    void*         C1;
    const __half* win;
    const float*  bias;
    const int*    perm;
    const int*    lenf_s;
    const int*    lenb_s;
    const int*    nt;
    const int*    operm;
    int M, N, K, step, Bn, zdir;
};

template<int MODE, int EPI, int OUTH>
__global__ __launch_bounds__(256, 2)
void gemm_f16(GemmP p)
{
    const int dir = (p.zdir >= 0) ? p.zdir : blockIdx.z;
    const int bm  = blockIdx.y;
    const int bn  = blockIdx.x;

    // ---- length-compaction early exit ----
    if (MODE == MODE_GATHER) {
        if (bm * 128 >= p.nt[dir * MAXL + p.step]) return;
    } else if (p.nt) {
        if (bm * 128 >= p.nt[dir * MAXL + p.step]) return;
    }

    extern __shared__ __half hsm[];
    __half* As = hsm;
    __half* Bs = hsm + STAGES * STAGE_HALFS;

    const __half* __restrict__ Bmat = dir ? p.B1 : p.B0;
    const int K = p.K;
    const int N = p.N;

    const int tid  = threadIdx.x;
    const int warp = tid >> 5;
    const int lane = tid & 31;
    const int wm   = (warp >> 1) * 32;
    const int wn   = (warp & 1) * 64;

    const int lr = tid >> 2;
    const int lc = (tid & 3) * 8;

    const __half* arow0 = nullptr;
    const __half* arow1 = nullptr;
    const __half* ab0 = nullptr;
    const __half* ab1 = nullptr;

    if (MODE == MODE_GATHER) {
        const int t = p.step;
        #pragma unroll
        for (int q = 0; q < 2; ++q) {
            const int i   = bm * 128 + lr + q * 64;
            const int b   = p.perm[i];
            const int len = dir ? p.lenb_s[i] : p.lenf_s[i];
            int idx = dir ? (6 + len - t) : (8 - len + t);
            idx = min(max(idx, 0), T_WIN - 1);
            const __half* rp = p.win + ((size_t)b * T_WIN + idx) * D_DIM;
            if (q == 0) arow0 = rp; else arow1 = rp;
        }
    } else if (MODE == MODE_PLAIN) {
        arow0 = (dir ? p.A1 : p.A0) + (size_t)(bm * 128 + lr) * K;
        arow1 = arow0 + (size_t)64 * K;
    } else {
        const int r0 = bm * 128 + lr;
        arow0 = p.A0 + (size_t)r0 * 512;
        arow1 = p.A0 + (size_t)(r0 + 64) * 512;
        ab0   = p.A1 + (size_t)r0 * 512;
        ab1   = p.A1 + (size_t)(r0 + 64) * 512;
    }

    const __half* brow0 = Bmat + (size_t)(bn * 128 + lr) * K;
    const __half* brow1 = brow0 + (size_t)64 * K;

    float acc[2][8][4];
    #pragma unroll
    for (int i = 0; i < 2; ++i)
        #pragma unroll
        for (int t = 0; t < 8; ++t)
            #pragma unroll
            for (int v = 0; v < 4; ++v) acc[i][t][v] = 0.f;

    const int KT = K >> 5;

#define LOAD_STAGE(S, KI)                                                      \
    do {                                                                       \
        if ((KI) < KT) {                                                       \
            const int K0 = (KI) * 32;                                          \
            __half* da = As + (S) * STAGE_HALFS + lr * PITCH_H + lc;           \
            __half* db = Bs + (S) * STAGE_HALFS + lr * PITCH_H + lc;           \
            const __half *pa0, *pa1;                                           \
            if (MODE == MODE_CONCAT) {                                         \
                pa0 = ((K0 < 512) ? arow0 : ab0) + (K0 & 511) + lc;            \
                pa1 = ((K0 < 512) ? arow1 : ab1) + (K0 & 511) + lc;            \
            } else {                                                           \
                pa0 = arow0 + K0 + lc;                                         \
                pa1 = arow1 + K0 + lc;                                         \
            }                                                                  \
            cpasync16(da,                pa0);                                 \
            cpasync16(da + 64 * PITCH_H, pa1);                                 \
            cpasync16(db,                brow0 + K0 + lc);                     \
            cpasync16(db + 64 * PITCH_H, brow1 + K0 + lc);                     \
        }                                                                      \
        CP_COMMIT();                                                           \
    } while (0)

    #pragma unroll
    for (int s = 0; s < STAGES - 1; ++s) LOAD_STAGE(s, s);

    for (int kt = 0; kt < KT; ++kt) {
        CP_WAIT(STAGES - 2);
        __syncthreads();

        const int buf = kt & (STAGES - 1);
        const __half* Ab = As + buf * STAGE_HALFS;
        const __half* Bb = Bs + buf * STAGE_HALFS;

        #pragma unroll
        for (int ks = 0; ks < 2; ++ks) {
            const int k0 = ks * 16;
            unsigned a[2][4];
            #pragma unroll
            for (int i = 0; i < 2; ++i)
                ldsm4(a[i], Ab + (wm + i * 16 + (lane & 15)) * PITCH_H
                               + k0 + (lane >> 4) * 8);
            unsigned b[4][4];
            #pragma unroll
            for (int t4 = 0; t4 < 4; ++t4)
                ldsm4(b[t4], Bb + (wn + t4 * 16 + ((lane >> 4) << 3)
                                   + (lane & 7)) * PITCH_H
                                + k0 + ((lane >> 3) & 1) * 8);
            #pragma unroll
            for (int i = 0; i < 2; ++i)
                #pragma unroll
                for (int t4 = 0; t4 < 4; ++t4) {
                    mma_f16(acc[i][2 * t4],     a[i], b[t4][0], b[t4][1]);
                    mma_f16(acc[i][2 * t4 + 1], a[i], b[t4][2], b[t4][3]);
                }
        }

        LOAD_STAGE((kt + STAGES - 1) & (STAGES - 1), kt + STAGES - 1);
    }
#undef LOAD_STAGE

    // ---- epilogue ----
    const int qr = lane >> 2;
    const int qc = (lane & 3) * 2;
    #pragma unroll
    for (int i = 0; i < 2; ++i) {
        const int rA = bm * 128 + wm + i * 16 + qr;
        const int gA = p.operm ? p.operm[rA]     : rA;
        const int gB = p.operm ? p.operm[rA + 8] : rA + 8;
        #pragma unroll
        for (int t = 0; t < 8; ++t) {
            const int cc = bn * 128 + wn + t * 8 + qc;
            float v0 = acc[i][t][0], v1 = acc[i][t][1];
            float v2 = acc[i][t][2], v3 = acc[i][t][3];
            if (EPI != EPI_NONE) {
                float b0 = p.bias[cc], b1 = p.bias[cc + 1];
                v0 += b0; v1 += b1; v2 += b0; v3 += b1;
                if (EPI == EPI_BIAS_RELU) {
                    v0 = fmaxf(v0, 0.f); v1 = fmaxf(v1, 0.f);
                    v2 = fmaxf(v2, 0.f); v3 = fmaxf(v3, 0.f);
                }
            }
            if (OUTH) {
                __half* Ch = (__half*)(dir ? p.C1 : p.C0);
                *(__half2*)(Ch + (size_t)gA * N + cc) = __floats2half2_rn(v0, v1);
                *(__half2*)(Ch + (size_t)gB * N + cc) = __floats2half2_rn(v2, v3);
            } else {
                float* Cf = (float*)(dir ? p.C1 : p.C0);
                *(float2*)(Cf + (size_t)gA * N + cc) = make_float2(v0, v1);
                *(float2*)(Cf + (size_t)gB * N + cc) = make_float2(v2, v3);
            }
        }
    }
}

// ---------------------------------------------------------------------------
// GRU gate update on sorted rows (prefix-active). xp/gh/h all fp16.
// zdir >= 0 pins direction (grid.z == 1).
// ---------------------------------------------------------------------------
struct GateP {
    const __half* xp0; const __half* xp1;
    const __half* gh0; const __half* gh1;
    __half*       h0;  __half*       h1;
    const float* bih0; const float* bih1;
    const float* bhh0; const float* bhh1;
    const int*   nt;
    int t, Bn, zdir;
};

__global__ void gru_gate(GateP p)
{
    const int dir = (p.zdir >= 0) ? p.zdir : blockIdx.z;
    const int gi  = blockIdx.x * blockDim.x + threadIdx.x;
    const int i   = gi >> 7;
    const int j   = (gi & 127) * 4;
    const int t   = p.t;

    if (i >= p.nt[dir * MAXL + t]) return;

    const __half* xp = (dir ? p.xp1 : p.xp0)
                     + ((size_t)t * p.Bn + i) * G3 + j;
    float4 xr = ldh4(xp);
    float4 xz = ldh4(xp + 512);
    float4 xn = ldh4(xp + 1024);

    const float* bih = (dir ? p.bih1 : p.bih0) + j;
    const float* bhh = (dir ? p.bhh1 : p.bhh0) + j;
    float4 br = *(const float4*)(bih);
    float4 bz = *(const float4*)(bih + 512);
    float4 bq = *(const float4*)(bih + 1024);
    float4 cr = *(const float4*)(bhh);
    float4 cz = *(const float4*)(bhh + 512);
    float4 cq = *(const float4*)(bhh + 1024);

    __half* hp = (dir ? p.h1 : p.h0) + (size_t)i * H_DIM + j;
    float4 hr, hz, hq, hv;
    if (t > 0) {
        const __half* gh = (dir ? p.gh1 : p.gh0) + (size_t)i * G3 + j;
        hr = ldh4(gh);
        hz = ldh4(gh + 512);
        hq = ldh4(gh + 1024);
        hv = ldh4(hp);
    } else {
        hr = hz = hq = make_float4(0.f, 0.f, 0.f, 0.f);
        hv = make_float4(0.f, 0.f, 0.f, 0.f);
    }

    float4 res;
#define GATE(c)                                                                \
    {                                                                          \
        float r = 1.f / (1.f + expf(-(xr.c + br.c + hr.c + cr.c)));            \
        float z = 1.f / (1.f + expf(-(xz.c + bz.c + hz.c + cz.c)));            \
        float n = tanhf(xn.c + bq.c + r * (hq.c + cq.c));                      \
        res.c = (1.f - z) * n + z * hv.c;                                      \
    }
    GATE(x) GATE(y) GATE(z) GATE(w)
#undef GATE
    *(__half2*)(hp)     = __floats2half2_rn(res.x, res.y);
    *(__half2*)(hp + 2) = __floats2half2_rn(res.z, res.w);
}

// ---------------------------------------------------------------------------
// Launch sequence (graph-capturable; gather side stream + split fwd/bwd chains)
// ---------------------------------------------------------------------------
extern "C" void kernel_launch(void* const* d_in, const int* in_sizes, int n_in,
                              void* d_out, int out_size)
{
    const float* win   = (const float*)d_in[0];
    const int*   wlen  = (const int*)  d_in[1];
    const float* Wih_f = (const float*)d_in[2];
    const float* Whh_f = (const float*)d_in[3];
    const float* bih_f = (const float*)d_in[4];
    const float* bhh_f = (const float*)d_in[5];
    const float* Wih_b = (const float*)d_in[6];
    const float* Whh_b = (const float*)d_in[7];
    const float* bih_b = (const float*)d_in[8];
    const float* bhh_b = (const float*)d_in[9];
    const float* W1    = (const float*)d_in[10];
    const float* b1    = (const float*)d_in[11];
    const float* W2    = (const float*)d_in[12];
    const float* b2    = (const float*)d_in[13];
    float* out = (float*)d_out;

    const int Bn = in_sizes[1];

    __half *xp0, *xp1, *gh0, *gh1, *h0, *h1, *hid, *winh, *wh;
    int *perm, *lenf_s, *lenb_s, *nt;
    cudaGetSymbolAddress((void**)&xp0,    g_xp0);
    cudaGetSymbolAddress((void**)&xp1,    g_xp1);
    cudaGetSymbolAddress((void**)&gh0,    g_gh0);
    cudaGetSymbolAddress((void**)&gh1,    g_gh1);
    cudaGetSymbolAddress((void**)&h0,     g_h0);
    cudaGetSymbolAddress((void**)&h1,     g_h1);
    cudaGetSymbolAddress((void**)&hid,    g_hid);
    cudaGetSymbolAddress((void**)&winh,   g_winh);
    cudaGetSymbolAddress((void**)&wh,     g_wh);
    cudaGetSymbolAddress((void**)&perm,   g_perm);
    cudaGetSymbolAddress((void**)&lenf_s, g_lenf_s);
    cudaGetSymbolAddress((void**)&lenb_s, g_lenb_s);
    cudaGetSymbolAddress((void**)&nt,     g_nt);

    static bool init_done = false;
    static cudaStream_t s2, s3;
    static cudaEvent_t  eFork, eG0, eBwd;
    static cudaEvent_t  eT[MAXL];
    if (!init_done) {
        cudaFuncSetAttribute(gemm_f16<MODE_GATHER, EPI_NONE, 1>,
                             cudaFuncAttributeMaxDynamicSharedMemorySize, SMEM_REQ);
        cudaFuncSetAttribute(gemm_f16<MODE_PLAIN, EPI_NONE, 1>,
                             cudaFuncAttributeMaxDynamicSharedMemorySize, SMEM_REQ);
        cudaFuncSetAttribute(gemm_f16<MODE_CONCAT, EPI_BIAS_RELU, 1>,
                             cudaFuncAttributeMaxDynamicSharedMemorySize, SMEM_REQ);
        cudaFuncSetAttribute(gemm_f16<MODE_PLAIN, EPI_BIAS, 0>,
                             cudaFuncAttributeMaxDynamicSharedMemorySize, SMEM_REQ);
        cudaStreamCreateWithFlags(&s2, cudaStreamNonBlocking);
        cudaStreamCreateWithFlags(&s3, cudaStreamNonBlocking);
        cudaEventCreateWithFlags(&eFork, cudaEventDisableTiming);
        cudaEventCreateWithFlags(&eG0,   cudaEventDisableTiming);
        cudaEventCreateWithFlags(&eBwd,  cudaEventDisableTiming);
        for (int t = 0; t < MAXL; ++t)
            cudaEventCreateWithFlags(&eT[t], cudaEventDisableTiming);
        init_done = true;
    }

    // --- 0a) Converts (main stream) ---
    {
        win2half<<<Bn * T_WIN, 128>>>((const float4*)win, (uint2*)winh, wlen);

        W6 w;
        w.src[0] = (const float4*)Wih_f; w.dst[0] = (uint4*)(wh + WH_WIHF);
        w.src[1] = (const float4*)Whh_f; w.dst[1] = (uint4*)(wh + WH_WHHF);
        w.src[2] = (const float4*)Wih_b; w.dst[2] = (uint4*)(wh + WH_WIHB);
        w.src[3] = (const float4*)Whh_b; w.dst[3] = (uint4*)(wh + WH_WHHB);
        w.src[4] = (const float4*)W1;    w.dst[4] = (uint4*)(wh + WH_W1);
        w.src[5] = (const float4*)W2;    w.dst[5] = (uint4*)(wh + WH_W2);
        w.n8[0] = w.n8[1] = w.n8[2] = w.n8[3] = G3 * D_DIM / 8;
        w.n8[4] = H_DIM * 2 * H_DIM / 8;
        w.n8[5] = H_DIM * H_DIM / 8;
        const int tot = 4 * (G3 * D_DIM / 8) + H_DIM * 2 * H_DIM / 8
                      + H_DIM * H_DIM / 8;
        weights2half<<<(tot + 255) / 256, 256>>>(w);
    }

    // --- 0b) Sort (main stream) ---
    const int nchunks = Bn / 256;
    sort1<<<nchunks, 256>>>(wlen);
    sort2<<<1, 32>>>(nchunks);
    sort3<<<nchunks, 256>>>(wlen);

    // --- fork: s2 (gathers) inherits converts+sort results ---
    cudaEventRecord(eFork, 0);
    cudaStreamWaitEvent(s2, eFork, 0);

    // --- 1) Per-timestep gather GEMMs ---
    GemmP p1 = {};
    p1.win = winh;
    p1.B0 = wh + WH_WIHF; p1.B1 = wh + WH_WIHB;
    p1.perm = perm; p1.lenf_s = lenf_s; p1.lenb_s = lenb_s; p1.nt = nt;
    p1.M = Bn; p1.N = G3; p1.K = D_DIM; p1.Bn = Bn; p1.zdir = -1;

    const dim3 ggrid_gemm(G3 / 128, Bn / 128, 2);

    // t=0 on main stream (both dirs)
    p1.step = 0;
    p1.C0 = xp0; p1.C1 = xp1;
    gemm_f16<MODE_GATHER, EPI_NONE, 1>
        <<<ggrid_gemm, 256, SMEM_REQ>>>(p1);
    cudaEventRecord(eG0, 0);

    // t=1..7 on s2
    for (int t = 1; t < MAXL; ++t) {
        p1.step = t;
        p1.C0 = xp0 + (size_t)t * Bn * G3;
        p1.C1 = xp1 + (size_t)t * Bn * G3;
        gemm_f16<MODE_GATHER, EPI_NONE, 1>
            <<<ggrid_gemm, 256, SMEM_REQ, s2>>>(p1);
        cudaEventRecord(eT[t], s2);
    }

    // --- 2) Recurrence: fwd chain on main, bwd chain on s3 ---
    GateP gp;
    gp.xp0 = xp0; gp.xp1 = xp1;
    gp.gh0 = gh0; gp.gh1 = gh1;
    gp.h0  = h0;  gp.h1  = h1;
    gp.bih0 = bih_f; gp.bih1 = bih_b;
    gp.bhh0 = bhh_f; gp.bhh1 = bhh_b;
    gp.nt = nt; gp.Bn = Bn;

    GemmP p2 = {};
    p2.A0 = h0; p2.A1 = h1;
    p2.B0 = wh + WH_WHHF; p2.B1 = wh + WH_WHHB;
    p2.C0 = gh0;          p2.C1 = gh1;
    p2.nt = nt;
    p2.M = Bn; p2.N = G3; p2.K = H_DIM; p2.Bn = Bn;

    const dim3 ggrid((Bn * (H_DIM / 4)) / 256, 1, 1);
    const dim3 rgrid(G3 / 128, Bn / 128, 1);

    // bwd chain start: s3 needs gather(0) output
    cudaStreamWaitEvent(s3, eG0, 0);

    // t=0 gates
    gp.t = 0;
    gp.zdir = 0;
    gru_gate<<<ggrid, 256>>>(gp);             // fwd on main
    gp.zdir = 1;
    gru_gate<<<ggrid, 256, 0, s3>>>(gp);      // bwd on s3

    for (int t = 1; t < MAXL; ++t) {
        // fwd: main
        p2.step = t; p2.zdir = 0;
        gemm_f16<MODE_PLAIN, EPI_NONE, 1><<<rgrid, 256, SMEM_REQ>>>(p2);
        cudaStreamWaitEvent(0, eT[t], 0);
        gp.t = t; gp.zdir = 0;
        gru_gate<<<ggrid, 256>>>(gp);

        // bwd: s3
        p2.zdir = 1;
        gemm_f16<MODE_PLAIN, EPI_NONE, 1><<<rgrid, 256, SMEM_REQ, s3>>>(p2);
        cudaStreamWaitEvent(s3, eT[t], 0);
        gp.zdir = 1;
        gru_gate<<<ggrid, 256, 0, s3>>>(gp);
    }
    cudaEventRecord(eBwd, s3);

    // --- 3) MLP on main (join bwd chain; s2 already joined via eT[7]) ---
    cudaStreamWaitEvent(0, eBwd, 0);

    GemmP p3 = {};
    p3.A0 = h0; p3.A1 = h1;
    p3.B0 = wh + WH_W1; p3.B1 = wh + WH_W1;
    p3.C0 = hid; p3.C1 = hid;
    p3.bias = b1;
    p3.M = Bn; p3.N = H_DIM; p3.K = 2 * H_DIM; p3.Bn = Bn; p3.zdir = -1;
    gemm_f16<MODE_CONCAT, EPI_BIAS_RELU, 1>
        <<<dim3(H_DIM / 128, Bn / 128, 1), 256, SMEM_REQ>>>(p3);

    GemmP p4 = {};
    p4.A0 = hid; p4.A1 = hid;
    p4.B0 = wh + WH_W2; p4.B1 = wh + WH_W2;
    p4.C0 = out; p4.C1 = out;
    p4.bias = b2;
    p4.operm = perm;
    p4.M = Bn; p4.N = H_DIM; p4.K = H_DIM; p4.Bn = Bn; p4.zdir = -1;
    gemm_f16<MODE_PLAIN, EPI_BIAS, 0>
        <<<dim3(H_DIM / 128, Bn / 128, 1), 256, SMEM_REQ>>>(p4);
}